// round 6
// baseline (speedup 1.0000x reference)
#include <cuda_runtime.h>

// Cost-volume correlation, MAX_DISP=4 (81 displacements), kernel_size=1.
// out[b, dy*9+dx, y, x] = (1/C) * sum_c in1[b,c,y,x] * in2[b,c,y+dy-4,x+dx-4]
//
// R6: occupancy fix. 512-thread blocks; threadIdx.z splits the 81 displacements
// into two balanced groups (40 / 41) so each thread carries <=41 f32x2
// accumulators (82 regs) instead of 81 (162 regs). Both groups share the same
// double-buffered in2 smem tile. Target: 16 warps/SM instead of 8.

typedef unsigned long long u64;

__device__ __forceinline__ u64 pk(float lo, float hi) {
    u64 r; asm("mov.b64 %0, {%1,%2};" : "=l"(r) : "f"(lo), "f"(hi)); return r;
}
__device__ __forceinline__ void upk(u64 v, float &lo, float &hi) {
    asm("mov.b64 {%0,%1}, %2;" : "=f"(lo), "=f"(hi) : "l"(v));
}
__device__ __forceinline__ void fma2(u64 &d, u64 a, u64 b) {
    asm("fma.rn.f32x2 %0, %1, %2, %0;" : "+l"(d) : "l"(a), "l"(b));
}

#define CC 128
#define HH 128
#define WW 128
#define HW (HH * WW)
#define NDISP 81
#define TILE_R 16            // 8 y-rows + 2*4 halo
#define TILE_C 72            // 64 x-pixels + 2*4 halo
#define TILE_N (TILE_R * TILE_C)   // 1152

// Group TZ=0: dy 0..3 all dx (36) + dy=4 dx 0..3 (4)  -> 40 accs, local l == disp
// Group TZ=1: dy=4 dx 4..8 (5)  + dy 5..8 all dx (36) -> 41 accs, disp = 40 + l
template<int TZ>
__device__ __forceinline__ void accum_rows(u64* __restrict__ acc,
                                           const float* __restrict__ base,
                                           u64 a2)
{
#pragma unroll
    for (int j = 0; j < 5; j++) {
        const int dy = TZ ? (4 + j) : j;
        const float2* rp = reinterpret_cast<const float2*>(base + dy * TILE_C);
        const bool full = TZ ? (j > 0) : (j < 4);
        if (full) {
            float2 p0 = rp[0], p1 = rp[1], p2 = rp[2], p3 = rp[3], p4 = rp[4];
            const int w0 = TZ ? (5 + (j - 1) * 9) : (j * 9);
            fma2(acc[w0 + 0], a2, pk(p0.x, p0.y));
            fma2(acc[w0 + 2], a2, pk(p1.x, p1.y));
            fma2(acc[w0 + 4], a2, pk(p2.x, p2.y));
            fma2(acc[w0 + 6], a2, pk(p3.x, p3.y));
            fma2(acc[w0 + 8], a2, pk(p4.x, p4.y));
            fma2(acc[w0 + 1], a2, pk(p0.y, p1.x));
            fma2(acc[w0 + 3], a2, pk(p1.y, p2.x));
            fma2(acc[w0 + 5], a2, pk(p2.y, p3.x));
            fma2(acc[w0 + 7], a2, pk(p3.y, p4.x));
        } else if (TZ == 0) {
            // dy=4, dx 0..3 -> window cols 0..4 -> p0,p1,p2.x
            float2 p0 = rp[0], p1 = rp[1], p2 = rp[2];
            fma2(acc[36 + 0], a2, pk(p0.x, p0.y));
            fma2(acc[36 + 2], a2, pk(p1.x, p1.y));
            fma2(acc[36 + 1], a2, pk(p0.y, p1.x));
            fma2(acc[36 + 3], a2, pk(p1.y, p2.x));
        } else {
            // dy=4, dx 4..8 -> window cols 4..9 -> p2,p3,p4
            float2 p2 = rp[2], p3 = rp[3], p4 = rp[4];
            fma2(acc[0], a2, pk(p2.x, p2.y));   // dx=4
            fma2(acc[2], a2, pk(p3.x, p3.y));   // dx=6
            fma2(acc[4], a2, pk(p4.x, p4.y));   // dx=8
            fma2(acc[1], a2, pk(p2.y, p3.x));   // dx=5
            fma2(acc[3], a2, pk(p3.y, p4.x));   // dx=7
        }
    }
}

__global__ __launch_bounds__(512, 1)
void corr_kernel(const float* __restrict__ in1,
                 const float* __restrict__ in2,
                 float* __restrict__ out)
{
    __shared__ float sm[2][TILE_N];

    const int tx  = threadIdx.x;                 // 0..31
    const int ty  = threadIdx.y;                 // 0..7
    const int tz  = threadIdx.z;                 // 0..1 displacement group
    const int tid = (tz * 8 + ty) * 32 + tx;     // 0..511
    const int x0  = blockIdx.x * 64;
    const int y0  = blockIdx.y * 8;
    const int b   = blockIdx.z;

    const int y = y0 + ty;
    const int x = x0 + tx * 2;                   // this thread: pixels x, x+1

    const float* i1 = in1 + ((b * CC) * HH + y) * WW + x;
    const float* i2 = in2 + (b * CC) * HW;

    u64 acc[41];
#pragma unroll
    for (int i = 0; i < 41; i++) acc[i] = 0ull;

    // Tile-load offsets + predicates (c-independent). 512 threads, 1152 elems.
    int  off[3];
    bool ok[3];
#pragma unroll
    for (int k = 0; k < 3; k++) {
        int i  = tid + k * 512;
        int r  = i / TILE_C;
        int cl = i - r * TILE_C;
        int gy = y0 - 4 + r;
        int gx = x0 - 4 + cl;
        ok[k]  = (i < TILE_N) && (gy >= 0) && (gy < HH) && (gx >= 0) && (gx < WW);
        off[k] = gy * WW + gx;
    }

    // Prologue: channel 0.
    float v[3];
#pragma unroll
    for (int k = 0; k < 3; k++) v[k] = ok[k] ? __ldg(i2 + off[k]) : 0.0f;
    float a0 = i1[0];
    float a1 = i1[1];
#pragma unroll
    for (int k = 0; k < 3; k++) {
        int i = tid + k * 512;
        if (i < TILE_N) sm[0][i] = v[k];
    }
    __syncthreads();

    int cur = 0;
    for (int c = 0; c < CC; c++) {
        // Prefetch next channel into registers.
        float vn[3];
        float a0n = 0.0f, a1n = 0.0f;
        const bool more = (c + 1 < CC);
        if (more) {
            const float* p = i2 + (c + 1) * HW;
#pragma unroll
            for (int k = 0; k < 3; k++) vn[k] = ok[k] ? __ldg(p + off[k]) : 0.0f;
            a0n = i1[(c + 1) * HW];
            a1n = i1[(c + 1) * HW + 1];
        } else {
#pragma unroll
            for (int k = 0; k < 3; k++) vn[k] = 0.0f;
        }

        const u64 a2 = pk(a0, a1);
        const float* base = &sm[cur][ty * TILE_C + tx * 2];   // col 0 = x-4

        if (tz == 0) accum_rows<0>(acc, base, a2);
        else         accum_rows<1>(acc, base, a2);

        if (more) {
#pragma unroll
            for (int k = 0; k < 3; k++) {
                int i = tid + k * 512;
                if (i < TILE_N) sm[cur ^ 1][i] = vn[k];
            }
            a0 = a0n;
            a1 = a1n;
        }
        __syncthreads();
        cur ^= 1;
    }

    // Epilogue: mean over C; disp = 40*tz + l. Group 0 has 40 accs, group 1 has 41.
    const float s = 1.0f / (float)CC;
    float* ob = out + ((b * NDISP + tz * 40) * HH + y) * WW + x;
#pragma unroll
    for (int l = 0; l < 41; l++) {
        if (l == 40 && tz == 0) break;
        float lo, hi;
        upk(acc[l], lo, hi);
        float2 o;
        o.x = lo * s;
        o.y = hi * s;
        *reinterpret_cast<float2*>(ob + l * HW) = o;
    }
}

extern "C" void kernel_launch(void* const* d_in, const int* in_sizes, int n_in,
                              void* d_out, int out_size)
{
    const float* in1 = (const float*)d_in[0];
    const float* in2 = (const float*)d_in[1];
    float* out = (float*)d_out;

    const int B = in_sizes[0] / (CC * HH * WW);   // 8

    dim3 block(32, 8, 2);
    dim3 grid(WW / 64, HH / 8, B);
    corr_kernel<<<grid, block>>>(in1, in2, out);
}

// round 7
// speedup vs baseline: 1.6224x; 1.6224x over previous
#include <cuda_runtime.h>
#include <cstdint>

// Cost-volume correlation, MAX_DISP=4 (81 disps), kernel_size=1.
// out[b, dy*9+dx, y, x] = (1/C) * sum_c in1[b,c,y,x] * in2[b,c,y+dy-4,x+dx-4]
//
// R7: grid-level dy split (3 dy rows / 27 disps per block) -> 54 acc regs,
// ~90 total, 2 CTAs/SM (16 warps) with NO spills. cp.async 16B tile staging,
// u64 smem loads feed fma.rn.f32x2 directly (no pack MOVs); odd-dx via scalar
// FFMA on free register halves.

typedef unsigned long long u64;

__device__ __forceinline__ void fma2(u64 &d, u64 a, u64 b) {
    asm("fma.rn.f32x2 %0, %1, %2, %0;" : "+l"(d) : "l"(a), "l"(b));
}
__device__ __forceinline__ u64 pk(float lo, float hi) {
    u64 r; asm("mov.b64 %0, {%1,%2};" : "=l"(r) : "f"(lo), "f"(hi)); return r;
}
__device__ __forceinline__ void upk(u64 v, float &lo, float &hi) {
    asm("mov.b64 {%0,%1}, %2;" : "=f"(lo), "=f"(hi) : "l"(v));
}

#define CC 128
#define HH 128
#define WW 128
#define HW (HH * WW)
#define NDISP 81
#define TILE_R 10            // 8 y-rows + 2 halo (3 dy values)
#define TILE_C 72            // 64 x-pixels + 8 halo
#define TILE_N (TILE_R * TILE_C)   // 720 floats = 2880 B
#define NQUAD (TILE_N / 4)         // 180 16-byte quads

__global__ __launch_bounds__(256, 2)
void corr_kernel(const float* __restrict__ in1,
                 const float* __restrict__ in2,
                 float* __restrict__ out)
{
    __shared__ __align__(16) float sm[2][TILE_N];

    const int tx  = threadIdx.x;             // 0..31
    const int ty  = threadIdx.y;             // 0..7
    const int tid = ty * 32 + tx;
    const int x0  = blockIdx.x * 64;
    const int y0  = blockIdx.y * 8;
    const int dyg = blockIdx.z % 3;          // dy group: dy = dyg*3 + j, j=0..2
    const int b   = blockIdx.z / 3;

    const int y = y0 + ty;
    const int x = x0 + tx * 2;               // pixels x, x+1

    const float* i1 = in1 + ((b * CC) * HH + y) * WW + x;

    // ---- 16B cp.async tile staging setup (1 quad per thread) ----
    // quad tid covers tile floats [tid*4, tid*4+4); row r = tid/18, col4 = (tid%18)*4
    // gx = x0-4+col4 is always 0 mod 4 -> quads are never partially OOB in x.
    const uint32_t sb = (uint32_t)__cvta_generic_to_shared(&sm[0][0]);
    const uint32_t dq = sb + tid * 16;       // buffer 0 dst; buffer 1 = +2880
    bool ok = false;
    const float* src = in2;
    {
        int r  = tid / 18;
        int c4 = (tid - r * 18) * 4;
        int gy = y0 - 4 + dyg * 3 + r;
        int gx = x0 - 4 + c4;
        ok  = (tid < NQUAD) && gy >= 0 && gy < HH && gx >= 0 && gx < WW;
        src = in2 + (b * CC) * HW + gy * WW + gx;
        if (tid < NQUAD && !ok) {            // zero never-copied slots, once
            float4 z = make_float4(0.f, 0.f, 0.f, 0.f);
            *(float4*)&sm[0][tid * 4] = z;
            *(float4*)&sm[1][tid * 4] = z;
        }
    }

    // issue channel 0 into buffer 0
    if (ok) asm volatile("cp.async.cg.shared.global [%0], [%1], 16;" :: "r"(dq), "l"(src));
    asm volatile("cp.async.commit_group;");
    float2 a = *(const float2*)i1;

    u64   accE[15];                          // even dx: 5 per dy row, packed pairs
    float accO[24];                          // odd dx:  4 per dy row, 2 scalars each
#pragma unroll
    for (int i = 0; i < 15; i++) accE[i] = 0ull;
#pragma unroll
    for (int i = 0; i < 24; i++) accO[i] = 0.f;

    int cur = 0;
    for (int c = 0; c < CC; c++) {
        asm volatile("cp.async.wait_group 0;" ::: "memory");
        __syncthreads();   // (a) channel-c tile visible to all; (b) buf cur^1 free

        // prefetch next channel (in1 regs + in2 cp.async into other buffer)
        float2 an = a;
        if (c + 1 < CC) {
            an = *(const float2*)(i1 + (c + 1) * HW);
            if (ok) {
                const float* s2 = src + (c + 1) * HW;
                uint32_t d2 = dq + (cur ^ 1) * (TILE_N * 4);
                asm volatile("cp.async.cg.shared.global [%0], [%1], 16;" :: "r"(d2), "l"(s2));
            }
        }
        asm volatile("cp.async.commit_group;");

        const float ax = a.x, ay = a.y;
        const u64 a2 = pk(ax, ay);
        const u64* base = (const u64*)&sm[cur][0];

#pragma unroll
        for (int j = 0; j < 3; j++) {
            const u64* rp = base + (ty + j) * (TILE_C / 2) + tx;  // window col0 = x-4
            u64 P0 = rp[0], P1 = rp[1], P2 = rp[2], P3 = rp[3], P4 = rp[4];
            // even dx = 2k: pair (in2[x-4+2k], in2[x-3+2k]) = Pk, direct
            fma2(accE[j * 5 + 0], a2, P0);
            fma2(accE[j * 5 + 1], a2, P1);
            fma2(accE[j * 5 + 2], a2, P2);
            fma2(accE[j * 5 + 3], a2, P3);
            fma2(accE[j * 5 + 4], a2, P4);
            // odd dx = 2t+1: lo half = Pk.hi * ax, hi half = P{k+1}.lo * ay
            float l0, h0, l1, h1, l2, h2, l3, h3, l4, h4;
            upk(P0, l0, h0); upk(P1, l1, h1); upk(P2, l2, h2);
            upk(P3, l3, h3); upk(P4, l4, h4);
            accO[j * 8 + 0] = fmaf(ax, h0, accO[j * 8 + 0]);
            accO[j * 8 + 1] = fmaf(ay, l1, accO[j * 8 + 1]);
            accO[j * 8 + 2] = fmaf(ax, h1, accO[j * 8 + 2]);
            accO[j * 8 + 3] = fmaf(ay, l2, accO[j * 8 + 3]);
            accO[j * 8 + 4] = fmaf(ax, h2, accO[j * 8 + 4]);
            accO[j * 8 + 5] = fmaf(ay, l3, accO[j * 8 + 5]);
            accO[j * 8 + 6] = fmaf(ax, h3, accO[j * 8 + 6]);
            accO[j * 8 + 7] = fmaf(ay, l4, accO[j * 8 + 7]);
        }

        a = an;
        cur ^= 1;
    }

    // ---- epilogue: mean over C, float2 stores ----
    const float s = 1.0f / (float)CC;
    float* ob = out + ((b * NDISP + dyg * 27) * HH + y) * WW + x;
#pragma unroll
    for (int j = 0; j < 3; j++) {
#pragma unroll
        for (int dx = 0; dx < 9; dx++) {
            float lo, hi;
            if ((dx & 1) == 0) {
                upk(accE[j * 5 + (dx >> 1)], lo, hi);
            } else {
                lo = accO[j * 8 + dx - 1];
                hi = accO[j * 8 + dx];
            }
            float2 o;
            o.x = lo * s;
            o.y = hi * s;
            *(float2*)(ob + (j * 9 + dx) * HW) = o;
        }
    }
}

extern "C" void kernel_launch(void* const* d_in, const int* in_sizes, int n_in,
                              void* d_out, int out_size)
{
    const float* in1 = (const float*)d_in[0];
    const float* in2 = (const float*)d_in[1];
    float* out = (float*)d_out;

    const int B = in_sizes[0] / (CC * HH * WW);   // 8

    dim3 block(32, 8);
    dim3 grid(WW / 64, HH / 8, B * 3);
    corr_kernel<<<grid, block>>>(in1, in2, out);
}

// round 8
// speedup vs baseline: 2.5125x; 1.5487x over previous
#include <cuda_runtime.h>
#include <cstdint>

// Cost-volume correlation, MAX_DISP=4 (81 disps), kernel_size=1.
// out[b, dy*9+dx, y, x] = (1/C) * sum_c in1[b,c,y,x] * in2[b,c,y+dy-4,x+dx-4]
//
// R8: R7 compute body + 4-stage cp.async pipeline (prefetch distance 3) and
// depth-2 in1 register prefetch, to hide DRAM latency that bounded R7
// (~1100 cyc/channel iteration with a 1-deep pipeline).

typedef unsigned long long u64;

__device__ __forceinline__ void fma2(u64 &d, u64 a, u64 b) {
    asm("fma.rn.f32x2 %0, %1, %2, %0;" : "+l"(d) : "l"(a), "l"(b));
}
__device__ __forceinline__ u64 pk(float lo, float hi) {
    u64 r; asm("mov.b64 %0, {%1,%2};" : "=l"(r) : "f"(lo), "f"(hi)); return r;
}
__device__ __forceinline__ void upk(u64 v, float &lo, float &hi) {
    asm("mov.b64 {%0,%1}, %2;" : "=f"(lo), "=f"(hi) : "l"(v));
}

#define CC 128
#define HH 128
#define WW 128
#define HW (HH * WW)
#define NDISP 81
#define TILE_R 10                  // 8 y-rows + 2 halo (3 dy values)
#define TILE_C 72                  // 64 x-pixels + 8 halo
#define TILE_N (TILE_R * TILE_C)   // 720 floats = 2880 B
#define NQUAD (TILE_N / 4)         // 180 16-byte quads
#define STAGES 4
#define STAGE_B (TILE_N * 4)       // bytes per stage

__global__ __launch_bounds__(256, 2)
void corr_kernel(const float* __restrict__ in1,
                 const float* __restrict__ in2,
                 float* __restrict__ out)
{
    __shared__ __align__(16) float sm[STAGES][TILE_N];

    const int tx  = threadIdx.x;             // 0..31
    const int ty  = threadIdx.y;             // 0..7
    const int tid = ty * 32 + tx;
    const int x0  = blockIdx.x * 64;
    const int y0  = blockIdx.y * 8;
    const int dyg = blockIdx.z % 3;          // dy = dyg*3 + j, j=0..2
    const int b   = blockIdx.z / 3;

    const int y = y0 + ty;
    const int x = x0 + tx * 2;               // pixels x, x+1

    const float* i1 = in1 + ((b * CC) * HH + y) * WW + x;

    // ---- 16B cp.async staging: 1 quad per thread, gx always 0 mod 4 ----
    const uint32_t sb = (uint32_t)__cvta_generic_to_shared(&sm[0][0]);
    const uint32_t dq = sb + tid * 16;       // stage-0 dst; stage s = +s*STAGE_B
    bool ok = false;
    const float* src = in2;
    {
        int r  = tid / 18;
        int c4 = (tid - r * 18) * 4;
        int gy = y0 - 4 + dyg * 3 + r;
        int gx = x0 - 4 + c4;
        ok  = (tid < NQUAD) && gy >= 0 && gy < HH && gx >= 0 && gx < WW;
        src = in2 + (b * CC) * HW + gy * WW + gx;
        if (tid < NQUAD && !ok) {            // zero never-copied slots in all stages
            float4 z = make_float4(0.f, 0.f, 0.f, 0.f);
#pragma unroll
            for (int s = 0; s < STAGES; s++)
                *(float4*)&sm[s][tid * 4] = z;
        }
    }

    // Prologue: issue channels 0..2 into stages 0..2 (one group each).
#pragma unroll
    for (int c = 0; c < 3; c++) {
        if (ok) {
            uint32_t d = dq + c * STAGE_B;
            const float* s = src + c * HW;
            asm volatile("cp.async.cg.shared.global [%0], [%1], 16;" :: "r"(d), "l"(s));
        }
        asm volatile("cp.async.commit_group;");
    }
    float2 aq0 = *(const float2*)i1;
    float2 aq1 = *(const float2*)(i1 + HW);

    u64   accE[15];                          // even dx: 5 per dy row (packed pairs)
    float accO[24];                          // odd dx:  4 per dy row (2 scalars)
#pragma unroll
    for (int i = 0; i < 15; i++) accE[i] = 0ull;
#pragma unroll
    for (int i = 0; i < 24; i++) accO[i] = 0.f;

    for (int c = 0; c < CC; c++) {
        asm volatile("cp.async.wait_group 2;" ::: "memory");
        __syncthreads();   // stage c%4 visible; stage (c+3)%4 (read at c-1) free

        // prefetch: in1 at distance 2, in2 at distance 3
        float2 an = make_float2(0.f, 0.f);
        if (c + 2 < CC) an = *(const float2*)(i1 + (c + 2) * HW);
        if (c + 3 < CC && ok) {
            uint32_t d = dq + ((c + 3) & 3) * STAGE_B;
            const float* s = src + (c + 3) * HW;
            asm volatile("cp.async.cg.shared.global [%0], [%1], 16;" :: "r"(d), "l"(s));
        }
        asm volatile("cp.async.commit_group;");

        const float ax = aq0.x, ay = aq0.y;
        const u64 a2 = pk(ax, ay);
        const u64* base = (const u64*)&sm[c & 3][0];

#pragma unroll
        for (int j = 0; j < 3; j++) {
            const u64* rp = base + (ty + j) * (TILE_C / 2) + tx;  // col0 = x-4
            u64 P0 = rp[0], P1 = rp[1], P2 = rp[2], P3 = rp[3], P4 = rp[4];
            // even dx = 2k: pair (in2[x-4+2k], in2[x-3+2k]) = Pk, direct
            fma2(accE[j * 5 + 0], a2, P0);
            fma2(accE[j * 5 + 1], a2, P1);
            fma2(accE[j * 5 + 2], a2, P2);
            fma2(accE[j * 5 + 3], a2, P3);
            fma2(accE[j * 5 + 4], a2, P4);
            // odd dx = 2t+1: lo = Pk.hi*ax, hi = P{k+1}.lo*ay
            float l0, h0, l1, h1, l2, h2, l3, h3, l4, h4;
            upk(P0, l0, h0); upk(P1, l1, h1); upk(P2, l2, h2);
            upk(P3, l3, h3); upk(P4, l4, h4);
            accO[j * 8 + 0] = fmaf(ax, h0, accO[j * 8 + 0]);
            accO[j * 8 + 1] = fmaf(ay, l1, accO[j * 8 + 1]);
            accO[j * 8 + 2] = fmaf(ax, h1, accO[j * 8 + 2]);
            accO[j * 8 + 3] = fmaf(ay, l2, accO[j * 8 + 3]);
            accO[j * 8 + 4] = fmaf(ax, h2, accO[j * 8 + 4]);
            accO[j * 8 + 5] = fmaf(ay, l3, accO[j * 8 + 5]);
            accO[j * 8 + 6] = fmaf(ax, h3, accO[j * 8 + 6]);
            accO[j * 8 + 7] = fmaf(ay, l4, accO[j * 8 + 7]);
        }

        aq0 = aq1;
        aq1 = an;
    }

    // ---- epilogue: mean over C, float2 stores ----
    const float s = 1.0f / (float)CC;
    float* ob = out + ((b * NDISP + dyg * 27) * HH + y) * WW + x;
#pragma unroll
    for (int j = 0; j < 3; j++) {
#pragma unroll
        for (int dx = 0; dx < 9; dx++) {
            float lo, hi;
            if ((dx & 1) == 0) {
                upk(accE[j * 5 + (dx >> 1)], lo, hi);
            } else {
                lo = accO[j * 8 + dx - 1];
                hi = accO[j * 8 + dx];
            }
            float2 o;
            o.x = lo * s;
            o.y = hi * s;
            *(float2*)(ob + (j * 9 + dx) * HW) = o;
        }
    }
}

extern "C" void kernel_launch(void* const* d_in, const int* in_sizes, int n_in,
                              void* d_out, int out_size)
{
    const float* in1 = (const float*)d_in[0];
    const float* in2 = (const float*)d_in[1];
    float* out = (float*)d_out;

    const int B = in_sizes[0] / (CC * HH * WW);   // 8

    dim3 block(32, 8);
    dim3 grid(WW / 64, HH / 8, B * 3);
    corr_kernel<<<grid, block>>>(in1, in2, out);
}